// round 13
// baseline (speedup 1.0000x reference)
#include <cuda_runtime.h>

#define A_    32
#define B_    32
#define KKA_  288
#define PS_   16
#define OH_   7
#define OW_   7
#define L_    49
#define NW_   4
#define NT_   128
#define W2SZ  (KKA_ * B_ * PS_)   // 147456 floats

typedef unsigned long long u64;

__device__ __constant__ float c_lam[3] = {0.0005f, 0.000975f, 0.00142625f};

// W transposed to [n][k(row)][o][4] so warp reads are coalesced
__device__ __align__(16) float W2g[W2SZ];

__global__ void wprep_kernel(const float* __restrict__ Wg) {
    int idx = blockIdx.x * 256 + threadIdx.x;
    if (idx < W2SZ) {
        int c = idx & 3;
        int o = (idx >> 2) & 31;
        int k = (idx >> 7) & 3;
        int n = idx >> 9;
        W2g[idx] = Wg[(n * 32 + o) * 16 + k * 4 + c];
    }
}

__device__ __forceinline__ u64 b2(float s) {
    u64 r; asm("mov.b64 %0,{%1,%1};" : "=l"(r) : "f"(s)); return r;
}
__device__ __forceinline__ u64 pk2(float x, float y) {
    u64 r; asm("mov.b64 %0,{%1,%2};" : "=l"(r) : "f"(x), "f"(y)); return r;
}
__device__ __forceinline__ u64 fma2(u64 a, u64 b, u64 c) {
    u64 d; asm("fma.rn.f32x2 %0,%1,%2,%3;" : "=l"(d) : "l"(a), "l"(b), "l"(c)); return d;
}
__device__ __forceinline__ u64 mul2(u64 a, u64 b) {
    u64 d; asm("mul.rn.f32x2 %0,%1,%2;" : "=l"(d) : "l"(a), "l"(b)); return d;
}
__device__ __forceinline__ u64 add2(u64 a, u64 b) {
    u64 d; asm("add.rn.f32x2 %0,%1,%2;" : "=l"(d) : "l"(a), "l"(b)); return d;
}
__device__ __forceinline__ void unpk(u64 a, float& x, float& y) {
    asm("mov.b64 {%0,%1},%2;" : "=f"(x), "=f"(y) : "l"(a));
}

// compute 8 packed votes for site-row set prp against W tile at wf; W regs transient
__device__ __forceinline__ void votes8(const float4* __restrict__ wf, int lane,
                                       const float4* __restrict__ prp, u64* v) {
    float4 q0 = wf[lane], q1 = wf[32 + lane], q2 = wf[64 + lane], q3 = wf[96 + lane];
    u64 w0a = pk2(q0.x, q0.y), w0b = pk2(q0.z, q0.w);
    u64 w1a = pk2(q1.x, q1.y), w1b = pk2(q1.z, q1.w);
    u64 w2a = pk2(q2.x, q2.y), w2b = pk2(q2.z, q2.w);
    u64 w3a = pk2(q3.x, q3.y), w3b = pk2(q3.z, q3.w);
    #pragma unroll
    for (int i = 0; i < 4; ++i) {
        float4 pr = prp[i];
        u64 v0, v1;
        v0 = mul2(b2(pr.x), w0a); v0 = fma2(b2(pr.y), w1a, v0);
        v0 = fma2(b2(pr.z), w2a, v0); v0 = fma2(b2(pr.w), w3a, v0);
        v1 = mul2(b2(pr.x), w0b); v1 = fma2(b2(pr.y), w1b, v1);
        v1 = fma2(b2(pr.z), w2b, v1); v1 = fma2(b2(pr.w), w3b, v1);
        v[2*i] = v0; v[2*i+1] = v1;
    }
}

__global__ void __launch_bounds__(NT_, 3)
convcaps_kernel(const float* __restrict__ a_in,
                const float* __restrict__ pose,
                const float* __restrict__ beta_u,
                const float* __restrict__ beta_a,
                float* __restrict__ out,
                int batch)
{
    __shared__ __align__(16) float pose_s[KKA_][PS_];   // [n][i*4+m]
    __shared__ float au_s[KKA_];
    __shared__ float S1s[PS_][B_];                      // [j][o]
    __shared__ float S2s[PS_][B_];
    __shared__ float rss[B_];
    __shared__ __align__(8) float c1s[8][B_][2];        // [jp][o][j&1] : -mu/sig
    __shared__ __align__(8) float c2s[8][B_][2];        // 0.5/sig
    __shared__ float lsg[PS_][B_];                      // log(sigma^2)
    __shared__ float c0s[PS_][B_];                      // 0.5*mu^2/sig
    __shared__ float base_s[B_];                        // per-o constant for ln_ap
    __shared__ float Mglob_s;                           // global softmax shift

    const int site = blockIdx.x;
    const int bb = site / L_;
    const int l  = site - bb * L_;
    const int oy = l / OW_, ox = l - oy * OW_;
    const int tid = threadIdx.x;
    const int wid = tid >> 5, lane = tid & 31;
    const int aout_total = batch * B_ * L_;

    // ---- load pose window (288 x 16) and activations (288) ----
    for (int idx = tid; idx < KKA_ * PS_; idx += NT_) {
        int n = idx >> 4, s = idx & 15;
        int p = n >> 5, a = n & 31;
        int ki = p / 3, kj = p - 3 * ki;
        pose_s[n][s] = pose[((bb * 512 + a * 16 + s) * 16 + 2 * oy + ki) * 16 + 2 * ox + kj];
    }
    for (int n = tid; n < KKA_; n += NT_) {
        int p = n >> 5, a = n & 31;
        int ki = p / 3, kj = p - 3 * ki;
        au_s[n] = a_in[((bb * 32 + a) * 16 + 2 * oy + ki) * 16 + 2 * ox + kj];
    }
    __syncthreads();

    const u64* c1p = (const u64*)c1s;
    const u64* c2p = (const u64*)c2s;

    for (int it = 0; it < 3; ++it) {
        for (int idx = tid; idx < PS_ * B_; idx += NT_) {
            ((float*)S1s)[idx] = 0.0f;
            ((float*)S2s)[idx] = 0.0f;
        }
        if (tid < B_) rss[tid] = 0.0f;
        __syncthreads();

        u64 a1[8], a2[8];
        #pragma unroll
        for (int k = 0; k < 8; ++k) { a1[k] = 0ull; a2[k] = 0ull; }
        float rs = 0.0f;

        if (it == 0) {
            #pragma unroll 2
            for (int n = wid; n < KKA_; n += NW_) {
                u64 v[8];
                votes8((const float4*)(W2g + n * 512), lane, (const float4*)pose_s[n], v);
                float au = au_s[n];
                u64 au2 = b2(au);
                rs += au;
                #pragma unroll
                for (int k = 0; k < 8; ++k) {
                    u64 u = mul2(au2, v[k]);
                    a1[k] = add2(a1[k], u);
                    a2[k] = fma2(u, v[k], a2[k]);
                }
            }
        } else {
            const float bm = base_s[lane] - Mglob_s;   // base - Mglob folded
            // per-o coefficients in registers (invariant over n)
            u64 cc1[8], cc2[8];
            #pragma unroll
            for (int k = 0; k < 8; ++k) {
                cc1[k] = c1p[k * B_ + lane];
                cc2[k] = c2p[k * B_ + lane];
            }
            // 4-way interleave; votes live across softmax, W transient
            #pragma unroll 1
            for (int n = wid; n < KKA_; n += 4 * NW_) {
                const int nB = n + NW_, nC = n + 2 * NW_, nD = n + 3 * NW_;
                u64 vA[8], vB[8], vC[8], vD[8];
                votes8((const float4*)(W2g + n  * 512), lane, (const float4*)pose_s[n],  vA);
                votes8((const float4*)(W2g + nB * 512), lane, (const float4*)pose_s[nB], vB);
                votes8((const float4*)(W2g + nC * 512), lane, (const float4*)pose_s[nC], vC);
                votes8((const float4*)(W2g + nD * 512), lane, (const float4*)pose_s[nD], vD);

                // Mahalanobis, 2 parallel chains per n, 4 n interleaved
                u64 aAx=0ull, aAy=0ull, aBx=0ull, aBy=0ull, aCx=0ull, aCy=0ull, aDx=0ull, aDy=0ull;
                #pragma unroll
                for (int k = 0; k < 8; k += 2) {
                    aAx = fma2(vA[k],   cc1[k],   aAx); aAx = fma2(mul2(vA[k],   vA[k]),   cc2[k],   aAx);
                    aAy = fma2(vA[k+1], cc1[k+1], aAy); aAy = fma2(mul2(vA[k+1], vA[k+1]), cc2[k+1], aAy);
                    aBx = fma2(vB[k],   cc1[k],   aBx); aBx = fma2(mul2(vB[k],   vB[k]),   cc2[k],   aBx);
                    aBy = fma2(vB[k+1], cc1[k+1], aBy); aBy = fma2(mul2(vB[k+1], vB[k+1]), cc2[k+1], aBy);
                    aCx = fma2(vC[k],   cc1[k],   aCx); aCx = fma2(mul2(vC[k],   vC[k]),   cc2[k],   aCx);
                    aCy = fma2(vC[k+1], cc1[k+1], aCy); aCy = fma2(mul2(vC[k+1], vC[k+1]), cc2[k+1], aCy);
                    aDx = fma2(vD[k],   cc1[k],   aDx); aDx = fma2(mul2(vD[k],   vD[k]),   cc2[k],   aDx);
                    aDy = fma2(vD[k+1], cc1[k+1], aDy); aDy = fma2(mul2(vD[k+1], vD[k+1]), cc2[k+1], aDy);
                }
                float x0, y0, x1, y1;
                unpk(aAx, x0, y0); unpk(aAy, x1, y1);
                float tA = bm - ((x0 + y0) + (x1 + y1));
                unpk(aBx, x0, y0); unpk(aBy, x1, y1);
                float tB = bm - ((x0 + y0) + (x1 + y1));
                unpk(aCx, x0, y0); unpk(aCy, x1, y1);
                float tC = bm - ((x0 + y0) + (x1 + y1));
                unpk(aDx, x0, y0); unpk(aDy, x1, y1);
                float tD = bm - ((x0 + y0) + (x1 + y1));

                float eA = __expf(tA), eB = __expf(tB), eC = __expf(tC), eD = __expf(tD);
                float sA = eA, sB = eB, sC = eC, sD = eD;
                #pragma unroll
                for (int d = 16; d; d >>= 1) {
                    sA += __shfl_xor_sync(0xffffffffu, sA, d);
                    sB += __shfl_xor_sync(0xffffffffu, sB, d);
                    sC += __shfl_xor_sync(0xffffffffu, sC, d);
                    sD += __shfl_xor_sync(0xffffffffu, sD, d);
                }
                float raA = eA * __fdividef(au_s[n],  fmaxf(sA, 1e-37f));
                float raB = eB * __fdividef(au_s[nB], fmaxf(sB, 1e-37f));
                float raC = eC * __fdividef(au_s[nC], fmaxf(sC, 1e-37f));
                float raD = eD * __fdividef(au_s[nD], fmaxf(sD, 1e-37f));
                rs += (raA + raB) + (raC + raD);
                u64 rA2 = b2(raA), rB2 = b2(raB), rC2 = b2(raC), rD2 = b2(raD);

                // phase B: accumulate moments from live votes
                #pragma unroll
                for (int k = 0; k < 8; ++k) {
                    u64 u;
                    u = mul2(rA2, vA[k]); a1[k] = add2(a1[k], u); a2[k] = fma2(u, vA[k], a2[k]);
                    u = mul2(rB2, vB[k]); a1[k] = add2(a1[k], u); a2[k] = fma2(u, vB[k], a2[k]);
                    u = mul2(rC2, vC[k]); a1[k] = add2(a1[k], u); a2[k] = fma2(u, vC[k], a2[k]);
                    u = mul2(rD2, vD[k]); a1[k] = add2(a1[k], u); a2[k] = fma2(u, vD[k], a2[k]);
                }
            }
        }

        #pragma unroll
        for (int k = 0; k < 8; ++k) {
            float x, y;
            unpk(a1[k], x, y);
            atomicAdd(&S1s[2*k][lane], x);
            atomicAdd(&S1s[2*k+1][lane], y);
            unpk(a2[k], x, y);
            atomicAdd(&S2s[2*k][lane], x);
            atomicAdd(&S2s[2*k+1][lane], y);
        }
        atomicAdd(&rss[lane], rs);
        __syncthreads();

        // ---- stage 2a: per (o,j) stats ----
        const bool last = (it == 2);
        for (int idx = tid; idx < PS_ * B_; idx += NT_) {
            int j = idx >> 5, o = idx & 31;
            float denom = rss[o] + 1e-12f;
            float m  = __fdividef(S1s[j][o], denom);
            float e2 = __fdividef(S2s[j][o], denom);
            float sig = fmaxf(e2 - m * m, 0.0f) + 1e-12f;
            lsg[j][o] = __logf(sig);
            if (last) {
                out[aout_total + ((bb * 512 + o * 16 + j) * OH_ + oy) * OW_ + ox] = m;
            } else {
                float inv = __fdividef(1.0f, sig);
                c1s[j >> 1][o][j & 1] = -m * inv;
                c2s[j >> 1][o][j & 1] = 0.5f * inv;
                c0s[j][o] = 0.5f * m * m * inv;
            }
        }
        __syncthreads();

        // ---- stage 2b: per-o activation (+ global softmax shift) ----
        if (tid < B_) {
            int o = tid;
            float SL = 0.0f, C0 = 0.0f;
            #pragma unroll
            for (int j = 0; j < PS_; ++j) { SL += lsg[j][o]; C0 += c0s[j][o]; }
            float cost = rss[o] * (16.0f * beta_u[o] + 0.5f * SL);
            float x = c_lam[it] * (beta_a[o] - cost);
            float a = 1.0f / (1.0f + __expf(-x));
            if (it == 2) {
                out[((bb * B_ + o) * OH_ + oy) * OW_ + ox] = a;
            } else {
                float base2 = __logf(a) - 0.5f * SL - 8.0f * 0.6086151514f;
                base_s[o] = base2 - C0;
                float mg = base2;
                #pragma unroll
                for (int d = 16; d; d >>= 1)
                    mg = fmaxf(mg, __shfl_xor_sync(0xffffffffu, mg, d));
                if (o == 0) Mglob_s = mg;
            }
        }
        __syncthreads();
    }
}

extern "C" void kernel_launch(void* const* d_in, const int* in_sizes, int n_in,
                              void* d_out, int out_size) {
    const float* a_in  = (const float*)d_in[0];
    const float* pose  = (const float*)d_in[1];
    const float* Wg    = (const float*)d_in[2];
    const float* bu    = (const float*)d_in[3];
    const float* ba    = (const float*)d_in[4];
    float* out = (float*)d_out;

    int batch = in_sizes[0] / (A_ * 16 * 16);   // 8
    int grid = batch * L_;                       // 392

    wprep_kernel<<<(W2SZ + 255) / 256, 256>>>(Wg);
    convcaps_kernel<<<grid, NT_>>>(a_in, pose, bu, ba, out, batch);
}

// round 14
// speedup vs baseline: 1.0408x; 1.0408x over previous
#include <cuda_runtime.h>

#define A_    32
#define B_    32
#define KKA_  288
#define PS_   16
#define OH_   7
#define OW_   7
#define L_    49
#define NW_   4
#define NT_   128
#define W2SZ  (KKA_ * B_ * PS_)   // 147456 floats

typedef unsigned long long u64;

__device__ __constant__ float c_lam[3] = {0.0005f, 0.000975f, 0.00142625f};

// W transposed to [n][k(row)][o][4] so warp reads are coalesced
__device__ __align__(16) float W2g[W2SZ];

__global__ void wprep_kernel(const float* __restrict__ Wg) {
    int idx = blockIdx.x * 256 + threadIdx.x;
    if (idx < W2SZ) {
        int c = idx & 3;
        int o = (idx >> 2) & 31;
        int k = (idx >> 7) & 3;
        int n = idx >> 9;
        W2g[idx] = Wg[(n * 32 + o) * 16 + k * 4 + c];
    }
}

__device__ __forceinline__ u64 b2(float s) {
    u64 r; asm("mov.b64 %0,{%1,%1};" : "=l"(r) : "f"(s)); return r;
}
__device__ __forceinline__ u64 pk2(float x, float y) {
    u64 r; asm("mov.b64 %0,{%1,%2};" : "=l"(r) : "f"(x), "f"(y)); return r;
}
__device__ __forceinline__ u64 fma2(u64 a, u64 b, u64 c) {
    u64 d; asm("fma.rn.f32x2 %0,%1,%2,%3;" : "=l"(d) : "l"(a), "l"(b), "l"(c)); return d;
}
__device__ __forceinline__ u64 mul2(u64 a, u64 b) {
    u64 d; asm("mul.rn.f32x2 %0,%1,%2;" : "=l"(d) : "l"(a), "l"(b)); return d;
}
__device__ __forceinline__ u64 add2(u64 a, u64 b) {
    u64 d; asm("add.rn.f32x2 %0,%1,%2;" : "=l"(d) : "l"(a), "l"(b)); return d;
}
__device__ __forceinline__ void unpk(u64 a, float& x, float& y) {
    asm("mov.b64 {%0,%1},%2;" : "=f"(x), "=f"(y) : "l"(a));
}

// compute 8 packed votes for site rows prp against W tile at wf; W regs transient
__device__ __forceinline__ void votes8(const float4* __restrict__ wf, int lane,
                                       const float4* __restrict__ prp, u64* v) {
    float4 q0 = wf[lane], q1 = wf[32 + lane], q2 = wf[64 + lane], q3 = wf[96 + lane];
    u64 w0a = pk2(q0.x, q0.y), w0b = pk2(q0.z, q0.w);
    u64 w1a = pk2(q1.x, q1.y), w1b = pk2(q1.z, q1.w);
    u64 w2a = pk2(q2.x, q2.y), w2b = pk2(q2.z, q2.w);
    u64 w3a = pk2(q3.x, q3.y), w3b = pk2(q3.z, q3.w);
    #pragma unroll
    for (int i = 0; i < 4; ++i) {
        float4 pr = prp[i];
        u64 v0, v1;
        v0 = mul2(b2(pr.x), w0a); v0 = fma2(b2(pr.y), w1a, v0);
        v0 = fma2(b2(pr.z), w2a, v0); v0 = fma2(b2(pr.w), w3a, v0);
        v1 = mul2(b2(pr.x), w0b); v1 = fma2(b2(pr.y), w1b, v1);
        v1 = fma2(b2(pr.z), w2b, v1); v1 = fma2(b2(pr.w), w3b, v1);
        v[2*i] = v0; v[2*i+1] = v1;
    }
}

__global__ void __launch_bounds__(NT_, 3)
convcaps_kernel(const float* __restrict__ a_in,
                const float* __restrict__ pose,
                const float* __restrict__ beta_u,
                const float* __restrict__ beta_a,
                float* __restrict__ out,
                int batch)
{
    __shared__ __align__(16) float pose_s[KKA_][PS_];   // [n][i*4+m]
    __shared__ float au_s[KKA_];
    __shared__ __align__(16) u64 P1[NW_][8][32];        // per-warp moment partials
    __shared__ __align__(16) u64 P2[NW_][8][32];
    __shared__ float rssp[NW_][32];
    __shared__ float rss[B_];
    __shared__ __align__(8) float c1s[8][B_][2];        // [jp][o][j&1] : -mu/sig
    __shared__ __align__(8) float c2s[8][B_][2];        // 0.5/sig
    __shared__ float lsg[PS_][B_];                      // log(sigma^2)
    __shared__ float c0s[PS_][B_];                      // 0.5*mu^2/sig
    __shared__ float base_s[B_];                        // per-o constant for ln_ap
    __shared__ float Mglob_s;                           // global softmax shift

    const int site = blockIdx.x;
    const int bb = site / L_;
    const int l  = site - bb * L_;
    const int oy = l / OW_, ox = l - oy * OW_;
    const int tid = threadIdx.x;
    const int wid = tid >> 5, lane = tid & 31;
    const int aout_total = batch * B_ * L_;

    // ---- load pose window (288 x 16) and activations (288) ----
    for (int idx = tid; idx < KKA_ * PS_; idx += NT_) {
        int n = idx >> 4, s = idx & 15;
        int p = n >> 5, a = n & 31;
        int ki = p / 3, kj = p - 3 * ki;
        pose_s[n][s] = pose[((bb * 512 + a * 16 + s) * 16 + 2 * oy + ki) * 16 + 2 * ox + kj];
    }
    for (int n = tid; n < KKA_; n += NT_) {
        int p = n >> 5, a = n & 31;
        int ki = p / 3, kj = p - 3 * ki;
        au_s[n] = a_in[((bb * 32 + a) * 16 + 2 * oy + ki) * 16 + 2 * ox + kj];
    }
    __syncthreads();

    const u64* c1p = (const u64*)c1s;
    const u64* c2p = (const u64*)c2s;

    for (int it = 0; it < 3; ++it) {
        u64 a1[8], a2[8];
        #pragma unroll
        for (int k = 0; k < 8; ++k) { a1[k] = 0ull; a2[k] = 0ull; }
        float rs = 0.0f;

        if (it == 0) {
            #pragma unroll 2
            for (int n = wid; n < KKA_; n += NW_) {
                u64 v[8];
                votes8((const float4*)(W2g + n * 512), lane, (const float4*)pose_s[n], v);
                float au = au_s[n];
                u64 au2 = b2(au);
                rs += au;
                #pragma unroll
                for (int k = 0; k < 8; ++k) {
                    u64 u = mul2(au2, v[k]);
                    a1[k] = add2(a1[k], u);
                    a2[k] = fma2(u, v[k], a2[k]);
                }
            }
        } else {
            const float bm = base_s[lane] - Mglob_s;   // base - Mglob folded
            u64 cc1[8], cc2[8];
            #pragma unroll
            for (int k = 0; k < 8; ++k) {
                cc1[k] = c1p[k * B_ + lane];
                cc2[k] = c2p[k * B_ + lane];
            }
            // 3-way interleave; votes live across softmax, W transient
            #pragma unroll 1
            for (int n = wid; n < KKA_; n += 3 * NW_) {
                const int nB = n + NW_, nC = n + 2 * NW_;
                u64 vA[8], vB[8], vC[8];
                votes8((const float4*)(W2g + n  * 512), lane, (const float4*)pose_s[n],  vA);
                votes8((const float4*)(W2g + nB * 512), lane, (const float4*)pose_s[nB], vB);
                votes8((const float4*)(W2g + nC * 512), lane, (const float4*)pose_s[nC], vC);

                // Mahalanobis: acc += v*(c2*v + c1)  (2 ops/pair)
                u64 aAx=0ull, aAy=0ull, aBx=0ull, aBy=0ull, aCx=0ull, aCy=0ull;
                #pragma unroll
                for (int k = 0; k < 8; k += 2) {
                    u64 t;
                    t = fma2(cc2[k],   vA[k],   cc1[k]);   aAx = fma2(vA[k],   t, aAx);
                    t = fma2(cc2[k+1], vA[k+1], cc1[k+1]); aAy = fma2(vA[k+1], t, aAy);
                    t = fma2(cc2[k],   vB[k],   cc1[k]);   aBx = fma2(vB[k],   t, aBx);
                    t = fma2(cc2[k+1], vB[k+1], cc1[k+1]); aBy = fma2(vB[k+1], t, aBy);
                    t = fma2(cc2[k],   vC[k],   cc1[k]);   aCx = fma2(vC[k],   t, aCx);
                    t = fma2(cc2[k+1], vC[k+1], cc1[k+1]); aCy = fma2(vC[k+1], t, aCy);
                }
                float x0, y0, x1, y1;
                unpk(aAx, x0, y0); unpk(aAy, x1, y1);
                float tA = bm - ((x0 + y0) + (x1 + y1));
                unpk(aBx, x0, y0); unpk(aBy, x1, y1);
                float tB = bm - ((x0 + y0) + (x1 + y1));
                unpk(aCx, x0, y0); unpk(aCy, x1, y1);
                float tC = bm - ((x0 + y0) + (x1 + y1));

                float eA = __expf(tA), eB = __expf(tB), eC = __expf(tC);
                float sA = eA, sB = eB, sC = eC;
                #pragma unroll
                for (int d = 16; d; d >>= 1) {
                    sA += __shfl_xor_sync(0xffffffffu, sA, d);
                    sB += __shfl_xor_sync(0xffffffffu, sB, d);
                    sC += __shfl_xor_sync(0xffffffffu, sC, d);
                }
                float raA = eA * __fdividef(au_s[n],  fmaxf(sA, 1e-37f));
                float raB = eB * __fdividef(au_s[nB], fmaxf(sB, 1e-37f));
                float raC = eC * __fdividef(au_s[nC], fmaxf(sC, 1e-37f));
                rs += raA + raB + raC;
                u64 rA2 = b2(raA), rB2 = b2(raB), rC2 = b2(raC);

                #pragma unroll
                for (int k = 0; k < 8; ++k) {
                    u64 u;
                    u = mul2(rA2, vA[k]); a1[k] = add2(a1[k], u); a2[k] = fma2(u, vA[k], a2[k]);
                    u = mul2(rB2, vB[k]); a1[k] = add2(a1[k], u); a2[k] = fma2(u, vB[k], a2[k]);
                    u = mul2(rC2, vC[k]); a1[k] = add2(a1[k], u); a2[k] = fma2(u, vC[k], a2[k]);
                }
            }
        }

        // per-warp partials (plain STS, no atomics)
        #pragma unroll
        for (int k = 0; k < 8; ++k) {
            P1[wid][k][lane] = a1[k];
            P2[wid][k][lane] = a2[k];
        }
        rssp[wid][lane] = rs;
        __syncthreads();

        // ---- stage 2a: per (o,j) stats ----
        const bool last = (it == 2);
        const float* p1f = (const float*)P1;
        const float* p2f = (const float*)P2;
        for (int idx = tid; idx < PS_ * B_; idx += NT_) {
            int j = idx >> 5, o = idx & 31;
            int k = j >> 1, h = j & 1;
            float S1 = 0.0f, S2v = 0.0f;
            #pragma unroll
            for (int w = 0; w < NW_; ++w) {
                int off = (((w * 8) + k) * 32 + o) * 2 + h;
                S1  += p1f[off];
                S2v += p2f[off];
            }
            float rsum = (rssp[0][o] + rssp[1][o]) + (rssp[2][o] + rssp[3][o]);
            float denom = rsum + 1e-12f;
            float m  = __fdividef(S1, denom);
            float e2 = __fdividef(S2v, denom);
            float sig = fmaxf(e2 - m * m, 0.0f) + 1e-12f;
            lsg[j][o] = __logf(sig);
            if (j == 0) rss[o] = rsum;
            if (last) {
                out[aout_total + ((bb * 512 + o * 16 + j) * OH_ + oy) * OW_ + ox] = m;
            } else {
                float inv = __fdividef(1.0f, sig);
                c1s[j >> 1][o][j & 1] = -m * inv;
                c2s[j >> 1][o][j & 1] = 0.5f * inv;
                c0s[j][o] = 0.5f * m * m * inv;
            }
        }
        __syncthreads();

        // ---- stage 2b: per-o activation (+ global softmax shift) ----
        if (tid < B_) {
            int o = tid;
            float SL = 0.0f, C0 = 0.0f;
            #pragma unroll
            for (int j = 0; j < PS_; ++j) { SL += lsg[j][o]; C0 += c0s[j][o]; }
            float cost = rss[o] * (16.0f * beta_u[o] + 0.5f * SL);
            float x = c_lam[it] * (beta_a[o] - cost);
            float a = 1.0f / (1.0f + __expf(-x));
            if (it == 2) {
                out[((bb * B_ + o) * OH_ + oy) * OW_ + ox] = a;
            } else {
                float base2 = __logf(a) - 0.5f * SL - 8.0f * 0.6086151514f;
                base_s[o] = base2 - C0;
                float mg = base2;
                #pragma unroll
                for (int d = 16; d; d >>= 1)
                    mg = fmaxf(mg, __shfl_xor_sync(0xffffffffu, mg, d));
                if (o == 0) Mglob_s = mg;
            }
        }
        __syncthreads();
    }
}

extern "C" void kernel_launch(void* const* d_in, const int* in_sizes, int n_in,
                              void* d_out, int out_size) {
    const float* a_in  = (const float*)d_in[0];
    const float* pose  = (const float*)d_in[1];
    const float* Wg    = (const float*)d_in[2];
    const float* bu    = (const float*)d_in[3];
    const float* ba    = (const float*)d_in[4];
    float* out = (float*)d_out;

    int batch = in_sizes[0] / (A_ * 16 * 16);   // 8
    int grid = batch * L_;                       // 392

    wprep_kernel<<<(W2SZ + 255) / 256, 256>>>(Wg);
    convcaps_kernel<<<grid, NT_>>>(a_in, pose, bu, ba, out, batch);
}

// round 15
// speedup vs baseline: 1.1097x; 1.0662x over previous
#include <cuda_runtime.h>

#define A_    32
#define B_    32
#define KKA_  288
#define PS_   16
#define OH_   7
#define OW_   7
#define L_    49
#define NW_   4
#define NT_   128
#define W2SZ  (KKA_ * B_ * PS_)   // 147456 floats

typedef unsigned long long u64;

__device__ __constant__ float c_lam[3] = {0.0005f, 0.000975f, 0.00142625f};

// W transposed to [n][k(row)][o][4] so warp reads are coalesced
__device__ __align__(16) float W2g[W2SZ];

__global__ void wprep_kernel(const float* __restrict__ Wg) {
    int idx = blockIdx.x * 256 + threadIdx.x;
    if (idx < W2SZ) {
        int c = idx & 3;
        int o = (idx >> 2) & 31;
        int k = (idx >> 7) & 3;
        int n = idx >> 9;
        W2g[idx] = Wg[(n * 32 + o) * 16 + k * 4 + c];
    }
}

__device__ __forceinline__ u64 b2(float s) {
    u64 r; asm("mov.b64 %0,{%1,%1};" : "=l"(r) : "f"(s)); return r;
}
__device__ __forceinline__ u64 pk2(float x, float y) {
    u64 r; asm("mov.b64 %0,{%1,%2};" : "=l"(r) : "f"(x), "f"(y)); return r;
}
__device__ __forceinline__ u64 fma2(u64 a, u64 b, u64 c) {
    u64 d; asm("fma.rn.f32x2 %0,%1,%2,%3;" : "=l"(d) : "l"(a), "l"(b), "l"(c)); return d;
}
__device__ __forceinline__ u64 mul2(u64 a, u64 b) {
    u64 d; asm("mul.rn.f32x2 %0,%1,%2;" : "=l"(d) : "l"(a), "l"(b)); return d;
}
__device__ __forceinline__ u64 add2(u64 a, u64 b) {
    u64 d; asm("add.rn.f32x2 %0,%1,%2;" : "=l"(d) : "l"(a), "l"(b)); return d;
}
__device__ __forceinline__ void unpk(u64 a, float& x, float& y) {
    asm("mov.b64 {%0,%1},%2;" : "=f"(x), "=f"(y) : "l"(a));
}

// load 4 W float4 rows for site n into q[off..off+3]
__device__ __forceinline__ void loadW(const float4* __restrict__ wf, int lane, float4* q) {
    q[0] = wf[lane]; q[1] = wf[32 + lane]; q[2] = wf[64 + lane]; q[3] = wf[96 + lane];
}

// votes from preloaded q[0..3] against pose rows prp -> v[8]
__device__ __forceinline__ void votesq(const float4* q, const float4* __restrict__ prp, u64* v) {
    u64 w0a = pk2(q[0].x, q[0].y), w0b = pk2(q[0].z, q[0].w);
    u64 w1a = pk2(q[1].x, q[1].y), w1b = pk2(q[1].z, q[1].w);
    u64 w2a = pk2(q[2].x, q[2].y), w2b = pk2(q[2].z, q[2].w);
    u64 w3a = pk2(q[3].x, q[3].y), w3b = pk2(q[3].z, q[3].w);
    #pragma unroll
    for (int i = 0; i < 4; ++i) {
        float4 pr = prp[i];
        u64 v0, v1;
        v0 = mul2(b2(pr.x), w0a); v0 = fma2(b2(pr.y), w1a, v0);
        v0 = fma2(b2(pr.z), w2a, v0); v0 = fma2(b2(pr.w), w3a, v0);
        v1 = mul2(b2(pr.x), w0b); v1 = fma2(b2(pr.y), w1b, v1);
        v1 = fma2(b2(pr.z), w2b, v1); v1 = fma2(b2(pr.w), w3b, v1);
        v[2*i] = v0; v[2*i+1] = v1;
    }
}

__global__ void __launch_bounds__(NT_, 3)
convcaps_kernel(const float* __restrict__ a_in,
                const float* __restrict__ pose,
                const float* __restrict__ beta_u,
                const float* __restrict__ beta_a,
                float* __restrict__ out,
                int batch)
{
    __shared__ __align__(16) float pose_s[KKA_][PS_];   // [n][i*4+m]
    __shared__ float au_s[KKA_];
    __shared__ __align__(16) u64 P1[NW_][8][32];        // per-warp moment partials
    __shared__ __align__(16) u64 P2[NW_][8][32];
    __shared__ float rssp[NW_][32];
    __shared__ float rss[B_];
    __shared__ __align__(8) float c1s[8][B_][2];        // [jp][o][j&1] : -mu/sig
    __shared__ __align__(8) float c2s[8][B_][2];        // 0.5/sig
    __shared__ float lsg[PS_][B_];                      // log(sigma^2)
    __shared__ float c0s[PS_][B_];                      // 0.5*mu^2/sig
    __shared__ float base_s[B_];                        // per-o constant for ln_ap
    __shared__ float Mglob_s;                           // global softmax shift

    const int site = blockIdx.x;
    const int bb = site / L_;
    const int l  = site - bb * L_;
    const int oy = l / OW_, ox = l - oy * OW_;
    const int tid = threadIdx.x;
    const int wid = tid >> 5, lane = tid & 31;
    const int aout_total = batch * B_ * L_;

    // ---- load pose window (288 x 16) and activations (288) ----
    for (int idx = tid; idx < KKA_ * PS_; idx += NT_) {
        int n = idx >> 4, s = idx & 15;
        int p = n >> 5, a = n & 31;
        int ki = p / 3, kj = p - 3 * ki;
        pose_s[n][s] = pose[((bb * 512 + a * 16 + s) * 16 + 2 * oy + ki) * 16 + 2 * ox + kj];
    }
    for (int n = tid; n < KKA_; n += NT_) {
        int p = n >> 5, a = n & 31;
        int ki = p / 3, kj = p - 3 * ki;
        au_s[n] = a_in[((bb * 32 + a) * 16 + 2 * oy + ki) * 16 + 2 * ox + kj];
    }
    __syncthreads();

    const u64* c1p = (const u64*)c1s;
    const u64* c2p = (const u64*)c2s;

    for (int it = 0; it < 3; ++it) {
        u64 a1[8], a2[8];
        #pragma unroll
        for (int k = 0; k < 8; ++k) { a1[k] = 0ull; a2[k] = 0ull; }
        float rs = 0.0f;

        if (it == 0) {
            #pragma unroll 2
            for (int n = wid; n < KKA_; n += NW_) {
                float4 q[4];
                loadW((const float4*)(W2g + n * 512), lane, q);
                u64 v[8];
                votesq(q, (const float4*)pose_s[n], v);
                float au = au_s[n];
                u64 au2 = b2(au);
                rs += au;
                #pragma unroll
                for (int k = 0; k < 8; ++k) {
                    u64 u = mul2(au2, v[k]);
                    a1[k] = add2(a1[k], u);
                    a2[k] = fma2(u, v[k], a2[k]);
                }
            }
        } else {
            const float bm = base_s[lane] - Mglob_s;   // base - Mglob folded
            u64 cc1[8], cc2[8];
            #pragma unroll
            for (int k = 0; k < 8; ++k) {
                cc1[k] = c1p[k * B_ + lane];
                cc2[k] = c2p[k * B_ + lane];
            }
            // 2-way interleave, software-pipelined W loads:
            // q holds next group's W; consumed by votes at loop top, reloaded
            // immediately so the LDG flies under maha/softmax/phaseB.
            float4 qA[4], qB[4];
            loadW((const float4*)(W2g + (size_t)wid * 512),          lane, qA);
            loadW((const float4*)(W2g + (size_t)(wid + NW_) * 512),  lane, qB);
            #pragma unroll 1
            for (int n = wid; n < KKA_; n += 2 * NW_) {
                const int nB = n + NW_;
                u64 vA[8], vB[8];
                votesq(qA, (const float4*)pose_s[n],  vA);
                votesq(qB, (const float4*)pose_s[nB], vB);

                // prefetch next group's W into the now-dead q registers
                int nn = n + 2 * NW_;
                int nnc = (nn < KKA_) ? nn : wid;     // clamp (harmless reload)
                loadW((const float4*)(W2g + (size_t)nnc * 512),          lane, qA);
                loadW((const float4*)(W2g + (size_t)(nnc + NW_) * 512),  lane, qB);

                // Mahalanobis: acc += v*(c2*v + c1)
                u64 aAx = 0ull, aAy = 0ull, aBx = 0ull, aBy = 0ull;
                #pragma unroll
                for (int k = 0; k < 8; k += 2) {
                    u64 t;
                    t = fma2(cc2[k],   vA[k],   cc1[k]);   aAx = fma2(vA[k],   t, aAx);
                    t = fma2(cc2[k+1], vA[k+1], cc1[k+1]); aAy = fma2(vA[k+1], t, aAy);
                    t = fma2(cc2[k],   vB[k],   cc1[k]);   aBx = fma2(vB[k],   t, aBx);
                    t = fma2(cc2[k+1], vB[k+1], cc1[k+1]); aBy = fma2(vB[k+1], t, aBy);
                }
                float x0, y0, x1, y1;
                unpk(aAx, x0, y0); unpk(aAy, x1, y1);
                float tA = bm - ((x0 + y0) + (x1 + y1));
                unpk(aBx, x0, y0); unpk(aBy, x1, y1);
                float tB = bm - ((x0 + y0) + (x1 + y1));

                float eA = __expf(tA), eB = __expf(tB);
                float sA = eA, sB = eB;
                #pragma unroll
                for (int d = 16; d; d >>= 1) {
                    sA += __shfl_xor_sync(0xffffffffu, sA, d);
                    sB += __shfl_xor_sync(0xffffffffu, sB, d);
                }
                float raA = eA * __fdividef(au_s[n],  fmaxf(sA, 1e-37f));
                float raB = eB * __fdividef(au_s[nB], fmaxf(sB, 1e-37f));
                rs += raA + raB;
                u64 rA2 = b2(raA), rB2 = b2(raB);

                #pragma unroll
                for (int k = 0; k < 8; ++k) {
                    u64 u;
                    u = mul2(rA2, vA[k]); a1[k] = add2(a1[k], u); a2[k] = fma2(u, vA[k], a2[k]);
                    u = mul2(rB2, vB[k]); a1[k] = add2(a1[k], u); a2[k] = fma2(u, vB[k], a2[k]);
                }
            }
        }

        // per-warp partials (plain STS, no atomics)
        #pragma unroll
        for (int k = 0; k < 8; ++k) {
            P1[wid][k][lane] = a1[k];
            P2[wid][k][lane] = a2[k];
        }
        rssp[wid][lane] = rs;
        __syncthreads();

        // ---- stage 2a: per (o,j) stats ----
        const bool last = (it == 2);
        const float* p1f = (const float*)P1;
        const float* p2f = (const float*)P2;
        for (int idx = tid; idx < PS_ * B_; idx += NT_) {
            int j = idx >> 5, o = idx & 31;
            int k = j >> 1, h = j & 1;
            float S1 = 0.0f, S2v = 0.0f;
            #pragma unroll
            for (int w = 0; w < NW_; ++w) {
                int off = (((w * 8) + k) * 32 + o) * 2 + h;
                S1  += p1f[off];
                S2v += p2f[off];
            }
            float rsum = (rssp[0][o] + rssp[1][o]) + (rssp[2][o] + rssp[3][o]);
            float denom = rsum + 1e-12f;
            float m  = __fdividef(S1, denom);
            float e2 = __fdividef(S2v, denom);
            float sig = fmaxf(e2 - m * m, 0.0f) + 1e-12f;
            lsg[j][o] = __logf(sig);
            if (j == 0) rss[o] = rsum;
            if (last) {
                out[aout_total + ((bb * 512 + o * 16 + j) * OH_ + oy) * OW_ + ox] = m;
            } else {
                float inv = __fdividef(1.0f, sig);
                c1s[j >> 1][o][j & 1] = -m * inv;
                c2s[j >> 1][o][j & 1] = 0.5f * inv;
                c0s[j][o] = 0.5f * m * m * inv;
            }
        }
        __syncthreads();

        // ---- stage 2b: per-o activation (+ global softmax shift) ----
        if (tid < B_) {
            int o = tid;
            float SL = 0.0f, C0 = 0.0f;
            #pragma unroll
            for (int j = 0; j < PS_; ++j) { SL += lsg[j][o]; C0 += c0s[j][o]; }
            float cost = rss[o] * (16.0f * beta_u[o] + 0.5f * SL);
            float x = c_lam[it] * (beta_a[o] - cost);
            float a = 1.0f / (1.0f + __expf(-x));
            if (it == 2) {
                out[((bb * B_ + o) * OH_ + oy) * OW_ + ox] = a;
            } else {
                float base2 = __logf(a) - 0.5f * SL - 8.0f * 0.6086151514f;
                base_s[o] = base2 - C0;
                float mg = base2;
                #pragma unroll
                for (int d = 16; d; d >>= 1)
                    mg = fmaxf(mg, __shfl_xor_sync(0xffffffffu, mg, d));
                if (o == 0) Mglob_s = mg;
            }
        }
        __syncthreads();
    }
}

extern "C" void kernel_launch(void* const* d_in, const int* in_sizes, int n_in,
                              void* d_out, int out_size) {
    const float* a_in  = (const float*)d_in[0];
    const float* pose  = (const float*)d_in[1];
    const float* Wg    = (const float*)d_in[2];
    const float* bu    = (const float*)d_in[3];
    const float* ba    = (const float*)d_in[4];
    float* out = (float*)d_out;

    int batch = in_sizes[0] / (A_ * 16 * 16);   // 8
    int grid = batch * L_;                       // 392

    wprep_kernel<<<(W2SZ + 255) / 256, 256>>>(Wg);
    convcaps_kernel<<<grid, NT_>>>(a_in, pose, bu, ba, out, batch);
}